// round 3
// baseline (speedup 1.0000x reference)
#include <cuda_runtime.h>
#include <cstdint>

#define N_NODES 100000
#define N_EDGES 1600000
#define IN_DIM  256
#define OUT_DIM 64

// Scratch (device globals: no allocation allowed in kernel_launch)
__device__ float g_X[(size_t)N_NODES * OUT_DIM];   // projected features, 25.6 MB
__device__ int   g_cnt[N_NODES];                   // histogram
__device__ int   g_offs[N_NODES + 1];              // CSR row offsets
__device__ int   g_cursor[N_NODES];                // fill cursors
__device__ int   g_sorted_cols[N_EDGES];           // cols sorted by row, 6.4 MB

// ---------------------------------------------------------------------------
// GEMM: X = inputs @ W  (100000x256 @ 256x64), fp32 via packed fma.rn.f32x2.
// 256 threads/block, thread computes 4 rows x 16 cols.
// ---------------------------------------------------------------------------
__global__ __launch_bounds__(256) void gemm_kernel(
    const float* __restrict__ in, const float* __restrict__ w)
{
    __shared__ float sw[IN_DIM * OUT_DIM];  // 64 KB

    {
        const float4* wsrc = (const float4*)w;
        float4* wdst = (float4*)sw;
        #pragma unroll
        for (int i = 0; i < 16; i++)
            wdst[threadIdx.x + i * 256] = wsrc[threadIdx.x + i * 256];
    }
    __syncthreads();

    const int colg = threadIdx.x & 3;
    const int rowg = threadIdx.x >> 2;
    const int row0 = blockIdx.x * 256 + rowg * 4;

    int r[4];
    #pragma unroll
    for (int i = 0; i < 4; i++) {
        int rr = row0 + i;
        r[i] = rr < N_NODES ? rr : (N_NODES - 1);
    }

    const float4* inp[4];
    #pragma unroll
    for (int i = 0; i < 4; i++)
        inp[i] = (const float4*)(in + (size_t)r[i] * IN_DIM);

    unsigned long long acc[4][8];
    #pragma unroll
    for (int i = 0; i < 4; i++)
        #pragma unroll
        for (int j = 0; j < 8; j++) acc[i][j] = 0ULL;

    #pragma unroll 2
    for (int k4 = 0; k4 < IN_DIM / 4; k4++) {
        float4 a4[4];
        #pragma unroll
        for (int i = 0; i < 4; i++) a4[i] = inp[i][k4];

        #pragma unroll
        for (int kk = 0; kk < 4; kk++) {
            const int k = k4 * 4 + kk;
            const ulonglong2* wrow =
                (const ulonglong2*)(sw + k * OUT_DIM + colg * 16);
            unsigned long long wp[8];
            #pragma unroll
            for (int j = 0; j < 4; j++) {
                ulonglong2 v = wrow[j];
                wp[2 * j]     = v.x;
                wp[2 * j + 1] = v.y;
            }
            #pragma unroll
            for (int i = 0; i < 4; i++) {
                float a = (kk == 0) ? a4[i].x : (kk == 1) ? a4[i].y
                        : (kk == 2) ? a4[i].z : a4[i].w;
                unsigned long long av;
                asm("mov.b64 %0, {%1,%1};" : "=l"(av) : "f"(a));
                #pragma unroll
                for (int j = 0; j < 8; j++)
                    asm("fma.rn.f32x2 %0, %1, %2, %0;"
                        : "+l"(acc[i][j]) : "l"(av), "l"(wp[j]));
            }
        }
    }

    #pragma unroll
    for (int i = 0; i < 4; i++) {
        int rr = row0 + i;
        if (rr < N_NODES) {
            ulonglong2* dst =
                (ulonglong2*)(g_X + (size_t)rr * OUT_DIM + colg * 16);
            dst[0] = make_ulonglong2(acc[i][0], acc[i][1]);
            dst[1] = make_ulonglong2(acc[i][2], acc[i][3]);
            dst[2] = make_ulonglong2(acc[i][4], acc[i][5]);
            dst[3] = make_ulonglong2(acc[i][6], acc[i][7]);
        }
    }
}

// ---------------------------------------------------------------------------
// Counting sort of edges by destination row
// ---------------------------------------------------------------------------
__global__ void zero_cnt_kernel()
{
    int i = blockIdx.x * blockDim.x + threadIdx.x;
    if (i < N_NODES) g_cnt[i] = 0;
}

__global__ __launch_bounds__(256) void hist_kernel(const int* __restrict__ rows)
{
    int e = blockIdx.x * blockDim.x + threadIdx.x;
    if (e < N_EDGES)
        atomicAdd(&g_cnt[rows[e]], 1);
}

// Single-block exclusive scan over g_cnt -> g_offs (+ copy to g_cursor)
__global__ __launch_bounds__(1024) void scan_kernel()
{
    __shared__ int ssum[1024];
    const int t = threadIdx.x;
    const int CH = (N_NODES + 1023) / 1024;  // 98
    const int lo = t * CH;
    const int hi = (lo + CH < N_NODES) ? lo + CH : N_NODES;

    int s = 0;
    for (int i = lo; i < hi; i++) s += g_cnt[i];
    ssum[t] = s;
    __syncthreads();

    // Hillis-Steele inclusive scan over 1024 partial sums
    for (int d = 1; d < 1024; d <<= 1) {
        int v = 0;
        if (t >= d) v = ssum[t - d];
        __syncthreads();
        if (t >= d) ssum[t] += v;
        __syncthreads();
    }

    int run = (t > 0) ? ssum[t - 1] : 0;  // exclusive base for this chunk
    for (int i = lo; i < hi; i++) {
        g_offs[i] = run;
        g_cursor[i] = run;
        run += g_cnt[i];
    }
    if (t == 1023) g_offs[N_NODES] = run;
}

__global__ __launch_bounds__(256) void fill_kernel(
    const int* __restrict__ rows, const int* __restrict__ cols)
{
    int e = blockIdx.x * blockDim.x + threadIdx.x;
    if (e < N_EDGES) {
        int r = rows[e];
        int pos = atomicAdd(&g_cursor[r], 1);
        g_sorted_cols[pos] = cols[e];
    }
}

// ---------------------------------------------------------------------------
// CSR aggregation + fused sigmoid. One warp per node.
// Each lane owns 2 consecutive output floats (float2): 32 lanes x 2 = 64.
// ---------------------------------------------------------------------------
__global__ __launch_bounds__(256) void aggregate_kernel(float* __restrict__ out)
{
    const int warp = threadIdx.x >> 5;
    const int lane = threadIdx.x & 31;
    const int node = blockIdx.x * 8 + warp;
    if (node >= N_NODES) return;

    const int start = g_offs[node];
    const int end   = g_offs[node + 1];

    float a0 = 0.f, a1 = 0.f;

    for (int base = start; base < end; base += 32) {
        const int idx = base + lane;
        const int c = (idx < end) ? g_sorted_cols[idx] : 0;
        const int nv = (end - base < 32) ? (end - base) : 32;
        #pragma unroll 4
        for (int j = 0; j < nv; j++) {
            const int cc = __shfl_sync(0xFFFFFFFFu, c, j);
            const float2 v =
                *(const float2*)(g_X + (size_t)cc * OUT_DIM + lane * 2);
            a0 += v.x;
            a1 += v.y;
        }
    }

    float2 o;
    o.x = 1.0f / (1.0f + __expf(-a0));
    o.y = 1.0f / (1.0f + __expf(-a1));
    *(float2*)(out + (size_t)node * OUT_DIM + lane * 2) = o;
}

extern "C" void kernel_launch(void* const* d_in, const int* in_sizes, int n_in,
                              void* d_out, int out_size)
{
    const float* inputs = (const float*)d_in[0];   // [100000, 256] f32
    const int*   eidx   = (const int*)d_in[1];     // [2, 1600000] int32
    const float* weight = (const float*)d_in[2];   // [256, 64] f32
    float*       out    = (float*)d_out;           // [100000, 64] f32

    const int* erows = eidx;
    const int* ecols = eidx + N_EDGES;

    // 1. zero histogram
    zero_cnt_kernel<<<(N_NODES + 255) / 256, 256>>>();
    // 2. histogram of destination rows
    hist_kernel<<<(N_EDGES + 255) / 256, 256>>>(erows);
    // 3. GEMM (independent of sort; interleaved here)
    gemm_kernel<<<(N_NODES + 255) / 256, 256>>>(inputs, weight);
    // 4. prefix scan -> offsets + cursors
    scan_kernel<<<1, 1024>>>();
    // 5. bucket-fill sorted cols
    fill_kernel<<<(N_EDGES + 255) / 256, 256>>>(erows, ecols);
    // 6. CSR aggregate + sigmoid (launch #6: profiled by -s 5 -c 1)
    aggregate_kernel<<<(N_NODES + 7) / 8, 256>>>(out);
}

// round 4
// speedup vs baseline: 1.7489x; 1.7489x over previous
#include <cuda_runtime.h>
#include <cstdint>

#define N_NODES 100000
#define N_EDGES 1600000
#define IN_DIM  256
#define OUT_DIM 64

#define SCAN_BLK  98            // ceil(100000 / 1024)
#define SCAN_CHUNK 1024

// Scratch (device globals: no allocation allowed in kernel_launch)
__device__ float g_X[(size_t)N_NODES * OUT_DIM];   // projected features, 25.6 MB
__device__ int   g_cnt[N_NODES];                   // histogram
__device__ int   g_offs[N_NODES + 1];              // CSR row offsets
__device__ int   g_cursor[N_NODES];                // fill cursors
__device__ int   g_sorted_cols[N_EDGES];           // cols sorted by row, 6.4 MB
__device__ int   g_bsum[SCAN_BLK];                 // per-block sums
__device__ int   g_bbase[SCAN_BLK];                // per-block exclusive bases

// ---------------------------------------------------------------------------
// GEMM: X = inputs @ W  (100000x256 @ 256x64), fp32 via packed fma.rn.f32x2.
// ---------------------------------------------------------------------------
__global__ __launch_bounds__(256) void gemm_kernel(
    const float* __restrict__ in, const float* __restrict__ w)
{
    __shared__ float sw[IN_DIM * OUT_DIM];  // 64 KB

    {
        const float4* wsrc = (const float4*)w;
        float4* wdst = (float4*)sw;
        #pragma unroll
        for (int i = 0; i < 16; i++)
            wdst[threadIdx.x + i * 256] = wsrc[threadIdx.x + i * 256];
    }
    __syncthreads();

    const int colg = threadIdx.x & 3;
    const int rowg = threadIdx.x >> 2;
    const int row0 = blockIdx.x * 256 + rowg * 4;

    int r[4];
    #pragma unroll
    for (int i = 0; i < 4; i++) {
        int rr = row0 + i;
        r[i] = rr < N_NODES ? rr : (N_NODES - 1);
    }

    const float4* inp[4];
    #pragma unroll
    for (int i = 0; i < 4; i++)
        inp[i] = (const float4*)(in + (size_t)r[i] * IN_DIM);

    unsigned long long acc[4][8];
    #pragma unroll
    for (int i = 0; i < 4; i++)
        #pragma unroll
        for (int j = 0; j < 8; j++) acc[i][j] = 0ULL;

    #pragma unroll 2
    for (int k4 = 0; k4 < IN_DIM / 4; k4++) {
        float4 a4[4];
        #pragma unroll
        for (int i = 0; i < 4; i++) a4[i] = inp[i][k4];

        #pragma unroll
        for (int kk = 0; kk < 4; kk++) {
            const int k = k4 * 4 + kk;
            const ulonglong2* wrow =
                (const ulonglong2*)(sw + k * OUT_DIM + colg * 16);
            unsigned long long wp[8];
            #pragma unroll
            for (int j = 0; j < 4; j++) {
                ulonglong2 v = wrow[j];
                wp[2 * j]     = v.x;
                wp[2 * j + 1] = v.y;
            }
            #pragma unroll
            for (int i = 0; i < 4; i++) {
                float a = (kk == 0) ? a4[i].x : (kk == 1) ? a4[i].y
                        : (kk == 2) ? a4[i].z : a4[i].w;
                unsigned long long av;
                asm("mov.b64 %0, {%1,%1};" : "=l"(av) : "f"(a));
                #pragma unroll
                for (int j = 0; j < 8; j++)
                    asm("fma.rn.f32x2 %0, %1, %2, %0;"
                        : "+l"(acc[i][j]) : "l"(av), "l"(wp[j]));
            }
        }
    }

    #pragma unroll
    for (int i = 0; i < 4; i++) {
        int rr = row0 + i;
        if (rr < N_NODES) {
            ulonglong2* dst =
                (ulonglong2*)(g_X + (size_t)rr * OUT_DIM + colg * 16);
            dst[0] = make_ulonglong2(acc[i][0], acc[i][1]);
            dst[1] = make_ulonglong2(acc[i][2], acc[i][3]);
            dst[2] = make_ulonglong2(acc[i][4], acc[i][5]);
            dst[3] = make_ulonglong2(acc[i][6], acc[i][7]);
        }
    }
}

// ---------------------------------------------------------------------------
// Counting sort of edges by destination row
// ---------------------------------------------------------------------------
__global__ void zero_cnt_kernel()
{
    int i = blockIdx.x * blockDim.x + threadIdx.x;
    if (i < N_NODES) g_cnt[i] = 0;
}

__global__ __launch_bounds__(256) void hist_kernel(const int* __restrict__ rows)
{
    int e = blockIdx.x * blockDim.x + threadIdx.x;
    if (e < N_EDGES)
        atomicAdd(&g_cnt[rows[e]], 1);
}

// Phase A: per-block (1024 counters) reduce -> g_bsum[blockIdx]
__global__ __launch_bounds__(256) void scanA_kernel()
{
    __shared__ int sred[8];
    const int t = threadIdx.x;
    const int i0 = blockIdx.x * SCAN_CHUNK + t * 4;

    int s = 0;
    #pragma unroll
    for (int j = 0; j < 4; j++)
        if (i0 + j < N_NODES) s += g_cnt[i0 + j];

    // warp reduce
    #pragma unroll
    for (int d = 16; d > 0; d >>= 1)
        s += __shfl_down_sync(0xFFFFFFFFu, s, d);
    if ((t & 31) == 0) sred[t >> 5] = s;
    __syncthreads();
    if (t < 8) {
        int v = sred[t];
        #pragma unroll
        for (int d = 4; d > 0; d >>= 1)
            v += __shfl_down_sync(0xFFu, v, d);
        if (t == 0) g_bsum[blockIdx.x] = v;
    }
}

// Phase B: tiny scan over 98 block sums (1 block, 128 threads)
__global__ __launch_bounds__(128) void scanB_kernel()
{
    __shared__ int s[128];
    const int t = threadIdx.x;
    int v = (t < SCAN_BLK) ? g_bsum[t] : 0;
    s[t] = v;
    __syncthreads();
    #pragma unroll
    for (int d = 1; d < 128; d <<= 1) {
        int u = (t >= d) ? s[t - d] : 0;
        __syncthreads();
        s[t] += u;
        __syncthreads();
    }
    if (t < SCAN_BLK) g_bbase[t] = s[t] - v;      // exclusive
    if (t == 127) g_offs[N_NODES] = s[127];        // total
}

// Phase C: local exclusive scan of each 1024-chunk + base -> offs & cursor
__global__ __launch_bounds__(256) void scanC_kernel()
{
    __shared__ int part[256];
    const int t = threadIdx.x;
    const int i0 = blockIdx.x * SCAN_CHUNK + t * 4;

    int c[4];
    int s = 0;
    #pragma unroll
    for (int j = 0; j < 4; j++) {
        c[j] = (i0 + j < N_NODES) ? g_cnt[i0 + j] : 0;
        s += c[j];
    }
    part[t] = s;
    __syncthreads();
    #pragma unroll
    for (int d = 1; d < 256; d <<= 1) {
        int u = (t >= d) ? part[t - d] : 0;
        __syncthreads();
        part[t] += u;
        __syncthreads();
    }

    int run = g_bbase[blockIdx.x] + part[t] - s;   // exclusive base for this thread
    #pragma unroll
    for (int j = 0; j < 4; j++) {
        if (i0 + j < N_NODES) {
            g_offs[i0 + j] = run;
            g_cursor[i0 + j] = run;
        }
        run += c[j];
    }
}

__global__ __launch_bounds__(256) void fill_kernel(
    const int* __restrict__ rows, const int* __restrict__ cols)
{
    int e = blockIdx.x * blockDim.x + threadIdx.x;
    if (e < N_EDGES) {
        int r = rows[e];
        int pos = atomicAdd(&g_cursor[r], 1);
        g_sorted_cols[pos] = cols[e];
    }
}

// ---------------------------------------------------------------------------
// CSR aggregation + fused sigmoid. One warp per node, lane owns float2.
// Column indices are warp-uniform broadcast loads (L1-hit); 4 X-row gathers
// kept in flight with dual accumulator pairs.
// ---------------------------------------------------------------------------
__global__ __launch_bounds__(256) void aggregate_kernel(float* __restrict__ out)
{
    const int warp = threadIdx.x >> 5;
    const int lane = threadIdx.x & 31;
    const int node = blockIdx.x * 8 + warp;
    if (node >= N_NODES) return;

    const int start = g_offs[node];
    const int end   = g_offs[node + 1];

    const float* Xl = g_X + lane * 2;

    float a0 = 0.f, a1 = 0.f, b0 = 0.f, b1 = 0.f;

    int idx = start;
    for (; idx + 4 <= end; idx += 4) {
        const int c0 = g_sorted_cols[idx];
        const int c1 = g_sorted_cols[idx + 1];
        const int c2 = g_sorted_cols[idx + 2];
        const int c3 = g_sorted_cols[idx + 3];
        const float2 v0 = *(const float2*)(Xl + (size_t)c0 * OUT_DIM);
        const float2 v1 = *(const float2*)(Xl + (size_t)c1 * OUT_DIM);
        const float2 v2 = *(const float2*)(Xl + (size_t)c2 * OUT_DIM);
        const float2 v3 = *(const float2*)(Xl + (size_t)c3 * OUT_DIM);
        a0 += v0.x; a1 += v0.y;
        b0 += v1.x; b1 += v1.y;
        a0 += v2.x; a1 += v2.y;
        b0 += v3.x; b1 += v3.y;
    }
    for (; idx < end; idx++) {
        const int c = g_sorted_cols[idx];
        const float2 v = *(const float2*)(Xl + (size_t)c * OUT_DIM);
        a0 += v.x; a1 += v.y;
    }
    a0 += b0; a1 += b1;

    float2 o;
    o.x = 1.0f / (1.0f + __expf(-a0));
    o.y = 1.0f / (1.0f + __expf(-a1));
    *(float2*)(out + (size_t)node * OUT_DIM + lane * 2) = o;
}

extern "C" void kernel_launch(void* const* d_in, const int* in_sizes, int n_in,
                              void* d_out, int out_size)
{
    const float* inputs = (const float*)d_in[0];   // [100000, 256] f32
    const int*   eidx   = (const int*)d_in[1];     // [2, 1600000] int32
    const float* weight = (const float*)d_in[2];   // [256, 64] f32
    float*       out    = (float*)d_out;           // [100000, 64] f32

    const int* erows = eidx;
    const int* ecols = eidx + N_EDGES;

    zero_cnt_kernel<<<(N_NODES + 255) / 256, 256>>>();
    hist_kernel<<<(N_EDGES + 255) / 256, 256>>>(erows);
    gemm_kernel<<<(N_NODES + 255) / 256, 256>>>(inputs, weight);
    scanA_kernel<<<SCAN_BLK, 256>>>();
    scanB_kernel<<<1, 128>>>();
    scanC_kernel<<<SCAN_BLK, 256>>>();
    fill_kernel<<<(N_EDGES + 255) / 256, 256>>>(erows, ecols);
    aggregate_kernel<<<(N_NODES + 7) / 8, 256>>>(out);
}

// round 5
// speedup vs baseline: 1.8135x; 1.0370x over previous
#include <cuda_runtime.h>
#include <cstdint>

#define N_NODES 100000
#define N_EDGES 1600000
#define IN_DIM  256
#define OUT_DIM 64

#define SCAN_BLK   98           // ceil(100000 / 1024)
#define SCAN_CHUNK 1024

// Scratch (device globals: no allocation allowed in kernel_launch).
// NOTE: g_cnt starts zeroed (static init) and is re-zeroed by aggregate_kernel
// at the end of every run, so each replay sees a zero histogram.
__device__ float g_X[(size_t)N_NODES * OUT_DIM];   // projected features, 25.6 MB
__device__ int   g_cnt[N_NODES];                   // histogram (self-resetting)
__device__ int   g_offs[N_NODES + 1];              // CSR row offsets
__device__ int   g_cursor[N_NODES];                // fill cursors
__device__ int   g_sorted_cols[N_EDGES];           // cols sorted by row, 6.4 MB
__device__ int   g_bsum[SCAN_BLK];                 // per-block sums

// ---------------------------------------------------------------------------
// GEMM: X = inputs @ W  (100000x256 @ 256x64), fp32 via packed fma.rn.f32x2.
// ---------------------------------------------------------------------------
__global__ __launch_bounds__(256) void gemm_kernel(
    const float* __restrict__ in, const float* __restrict__ w)
{
    __shared__ float sw[IN_DIM * OUT_DIM];  // 64 KB

    {
        const float4* wsrc = (const float4*)w;
        float4* wdst = (float4*)sw;
        #pragma unroll
        for (int i = 0; i < 16; i++)
            wdst[threadIdx.x + i * 256] = wsrc[threadIdx.x + i * 256];
    }
    __syncthreads();

    const int colg = threadIdx.x & 3;
    const int rowg = threadIdx.x >> 2;
    const int row0 = blockIdx.x * 256 + rowg * 4;

    int r[4];
    #pragma unroll
    for (int i = 0; i < 4; i++) {
        int rr = row0 + i;
        r[i] = rr < N_NODES ? rr : (N_NODES - 1);
    }

    const float4* inp[4];
    #pragma unroll
    for (int i = 0; i < 4; i++)
        inp[i] = (const float4*)(in + (size_t)r[i] * IN_DIM);

    unsigned long long acc[4][8];
    #pragma unroll
    for (int i = 0; i < 4; i++)
        #pragma unroll
        for (int j = 0; j < 8; j++) acc[i][j] = 0ULL;

    #pragma unroll 2
    for (int k4 = 0; k4 < IN_DIM / 4; k4++) {
        float4 a4[4];
        #pragma unroll
        for (int i = 0; i < 4; i++) a4[i] = inp[i][k4];

        #pragma unroll
        for (int kk = 0; kk < 4; kk++) {
            const int k = k4 * 4 + kk;
            const ulonglong2* wrow =
                (const ulonglong2*)(sw + k * OUT_DIM + colg * 16);
            unsigned long long wp[8];
            #pragma unroll
            for (int j = 0; j < 4; j++) {
                ulonglong2 v = wrow[j];
                wp[2 * j]     = v.x;
                wp[2 * j + 1] = v.y;
            }
            #pragma unroll
            for (int i = 0; i < 4; i++) {
                float a = (kk == 0) ? a4[i].x : (kk == 1) ? a4[i].y
                        : (kk == 2) ? a4[i].z : a4[i].w;
                unsigned long long av;
                asm("mov.b64 %0, {%1,%1};" : "=l"(av) : "f"(a));
                #pragma unroll
                for (int j = 0; j < 8; j++)
                    asm("fma.rn.f32x2 %0, %1, %2, %0;"
                        : "+l"(acc[i][j]) : "l"(av), "l"(wp[j]));
            }
        }
    }

    #pragma unroll
    for (int i = 0; i < 4; i++) {
        int rr = row0 + i;
        if (rr < N_NODES) {
            ulonglong2* dst =
                (ulonglong2*)(g_X + (size_t)rr * OUT_DIM + colg * 16);
            dst[0] = make_ulonglong2(acc[i][0], acc[i][1]);
            dst[1] = make_ulonglong2(acc[i][2], acc[i][3]);
            dst[2] = make_ulonglong2(acc[i][4], acc[i][5]);
            dst[3] = make_ulonglong2(acc[i][6], acc[i][7]);
        }
    }
}

// ---------------------------------------------------------------------------
// Counting sort of edges by destination row
// ---------------------------------------------------------------------------
__global__ __launch_bounds__(256) void hist_kernel(const int* __restrict__ rows)
{
    int e = blockIdx.x * blockDim.x + threadIdx.x;
    if (e < N_EDGES)
        atomicAdd(&g_cnt[rows[e]], 1);
}

// Phase A: per-1024-chunk reduce -> g_bsum[blockIdx]
__global__ __launch_bounds__(256) void scanA_kernel()
{
    __shared__ int sred[8];
    const int t = threadIdx.x;
    const int i0 = blockIdx.x * SCAN_CHUNK + t * 4;

    int s = 0;
    #pragma unroll
    for (int j = 0; j < 4; j++)
        if (i0 + j < N_NODES) s += g_cnt[i0 + j];

    #pragma unroll
    for (int d = 16; d > 0; d >>= 1)
        s += __shfl_down_sync(0xFFFFFFFFu, s, d);
    if ((t & 31) == 0) sred[t >> 5] = s;
    __syncthreads();
    if (t < 8) {
        int v = sred[t];
        #pragma unroll
        for (int d = 4; d > 0; d >>= 1)
            v += __shfl_down_sync(0xFFu, v, d);
        if (t == 0) g_bsum[blockIdx.x] = v;
    }
}

// Phase C: each block computes its exclusive base from the 98 block sums,
// then does the local exclusive scan of its 1024 counters -> offs & cursor.
__global__ __launch_bounds__(256) void scanC_kernel()
{
    __shared__ int part[256];
    __shared__ int sbase;
    const int t = threadIdx.x;

    // Base = sum of bsum[i] for i < blockIdx.x  (blockIdx.x <= 97 < 256)
    part[t] = (t < blockIdx.x) ? g_bsum[t] : 0;
    __syncthreads();
    #pragma unroll
    for (int d = 128; d > 0; d >>= 1) {
        if (t < d) part[t] += part[t + d];
        __syncthreads();
    }
    if (t == 0) sbase = part[0];
    __syncthreads();
    const int base = sbase;
    __syncthreads();

    // Local exclusive scan over this block's 1024 counters (4 per thread)
    const int i0 = blockIdx.x * SCAN_CHUNK + t * 4;
    int c[4];
    int s = 0;
    #pragma unroll
    for (int j = 0; j < 4; j++) {
        c[j] = (i0 + j < N_NODES) ? g_cnt[i0 + j] : 0;
        s += c[j];
    }
    part[t] = s;
    __syncthreads();
    #pragma unroll
    for (int d = 1; d < 256; d <<= 1) {
        int u = (t >= d) ? part[t - d] : 0;
        __syncthreads();
        part[t] += u;
        __syncthreads();
    }

    int run = base + part[t] - s;
    #pragma unroll
    for (int j = 0; j < 4; j++) {
        if (i0 + j < N_NODES) {
            g_offs[i0 + j] = run;
            g_cursor[i0 + j] = run;
        }
        run += c[j];
    }
    if (blockIdx.x == 0 && t == 0) g_offs[N_NODES] = N_EDGES;
}

__global__ __launch_bounds__(256) void fill_kernel(
    const int* __restrict__ rows, const int* __restrict__ cols)
{
    int e = blockIdx.x * blockDim.x + threadIdx.x;
    if (e < N_EDGES) {
        int r = rows[e];
        int pos = atomicAdd(&g_cursor[r], 1);
        g_sorted_cols[pos] = cols[e];
    }
}

// ---------------------------------------------------------------------------
// CSR aggregation + fused sigmoid. HALF-warp per node: 16 lanes x float4 = 64.
// 4 LDG.128 gathers in flight, dual accumulators. Also resets g_cnt for the
// next replay (histogram self-reset).
// ---------------------------------------------------------------------------
__global__ __launch_bounds__(256) void aggregate_kernel(float* __restrict__ out)
{
    const int hw   = threadIdx.x >> 4;       // 16 half-warps per block
    const int hl   = threadIdx.x & 15;       // lane within half-warp
    const int node = blockIdx.x * 16 + hw;
    if (node >= N_NODES) return;

    const int start = g_offs[node];
    const int end   = g_offs[node + 1];
    if (hl == 0) g_cnt[node] = 0;            // reset histogram for next run

    const float* Xl = g_X + hl * 4;

    float4 A = make_float4(0.f, 0.f, 0.f, 0.f);
    float4 B = make_float4(0.f, 0.f, 0.f, 0.f);

    int idx = start;
    for (; idx + 4 <= end; idx += 4) {
        const int c0 = g_sorted_cols[idx];
        const int c1 = g_sorted_cols[idx + 1];
        const int c2 = g_sorted_cols[idx + 2];
        const int c3 = g_sorted_cols[idx + 3];
        const float4 v0 = *(const float4*)(Xl + (size_t)c0 * OUT_DIM);
        const float4 v1 = *(const float4*)(Xl + (size_t)c1 * OUT_DIM);
        const float4 v2 = *(const float4*)(Xl + (size_t)c2 * OUT_DIM);
        const float4 v3 = *(const float4*)(Xl + (size_t)c3 * OUT_DIM);
        A.x += v0.x; A.y += v0.y; A.z += v0.z; A.w += v0.w;
        B.x += v1.x; B.y += v1.y; B.z += v1.z; B.w += v1.w;
        A.x += v2.x; A.y += v2.y; A.z += v2.z; A.w += v2.w;
        B.x += v3.x; B.y += v3.y; B.z += v3.z; B.w += v3.w;
    }
    for (; idx < end; idx++) {
        const int c = g_sorted_cols[idx];
        const float4 v = *(const float4*)(Xl + (size_t)c * OUT_DIM);
        A.x += v.x; A.y += v.y; A.z += v.z; A.w += v.w;
    }
    A.x += B.x; A.y += B.y; A.z += B.z; A.w += B.w;

    float4 o;
    o.x = 1.0f / (1.0f + __expf(-A.x));
    o.y = 1.0f / (1.0f + __expf(-A.y));
    o.z = 1.0f / (1.0f + __expf(-A.z));
    o.w = 1.0f / (1.0f + __expf(-A.w));
    *(float4*)(out + (size_t)node * OUT_DIM + hl * 4) = o;
}

extern "C" void kernel_launch(void* const* d_in, const int* in_sizes, int n_in,
                              void* d_out, int out_size)
{
    const float* inputs = (const float*)d_in[0];   // [100000, 256] f32
    const int*   eidx   = (const int*)d_in[1];     // [2, 1600000] int32
    const float* weight = (const float*)d_in[2];   // [256, 64] f32
    float*       out    = (float*)d_out;           // [100000, 64] f32

    const int* erows = eidx;
    const int* ecols = eidx + N_EDGES;

    // g_cnt is zero on entry (static init on first run, self-reset afterwards)
    hist_kernel<<<(N_EDGES + 255) / 256, 256>>>(erows);               // 1
    gemm_kernel<<<(N_NODES + 255) / 256, 256>>>(inputs, weight);      // 2
    scanA_kernel<<<SCAN_BLK, 256>>>();                                // 3
    scanC_kernel<<<SCAN_BLK, 256>>>();                                // 4
    fill_kernel<<<(N_EDGES + 255) / 256, 256>>>(erows, ecols);        // 5
    aggregate_kernel<<<(N_NODES + 15) / 16, 256>>>(out);              // 6 (profiled)
}